// round 1
// baseline (speedup 1.0000x reference)
#include <cuda_runtime.h>

// Integrate-and-fire: per neuron sequential scan over T=200 (two independent
// chunks of 100, membrane resets at chunk boundary).
//   v += x[t]; if (v > 2.0f) { spike = 1; v = 0; }
// Output is the per-timestep spike map transposed: in offset h*512 + wc,
// out offset wc*64 + h  (wc = w*8+c). So each timestep is a 64x512 transpose.
// We fuse the scan with a 32x32 smem tile transpose, unroll t by 4 with
// prefetch of the next group's loads to hide DRAM latency.

namespace {
constexpr int kT     = 200;
constexpr int kH     = 64;
constexpr int kWC    = 512;                    // W*C = 64*8
constexpr int kChunk = 100;
constexpr int kNPB   = kH * kWC;               // 32768 neurons per batch
constexpr long long kBS = (long long)kT * kNPB; // batch stride (elements)
constexpr int kGroup = 4;                      // timesteps per super-iteration
constexpr float kTh  = 2.0f;
}

__global__ void __launch_bounds__(256)
integrator_kernel(const float* __restrict__ in, float* __restrict__ out) {
    // +1 pad -> conflict-free for both row-major STS and column LDS
    __shared__ float sm[kGroup][32][33];

    const int tid = threadIdx.x;
    const int row = tid >> 3;      // 0..31
    const int q   = tid & 7;       // 0..7  (quad of 4 consecutive elements)
    const int wc0 = blockIdx.x * 32;
    const int h0  = blockIdx.y * 32;
    const int b   = blockIdx.z >> 1;
    const int t0  = (blockIdx.z & 1) * kChunk;

    // Read side: neuron (h = h0+row, wc = wc0 + q*4 .. +3), coalesced float4.
    const float* pin = in + b * kBS + (long long)t0 * kNPB
                          + (h0 + row) * kWC + wc0 + q * 4;
    // Write side (transposed): out[.., wc, h] = [.., (wc0+row)*64 + h0 + q*4 ..]
    float* pout = out + b * kBS + (long long)t0 * kNPB
                      + (wc0 + row) * 64 + h0 + q * 4;

    float v0 = 0.f, v1 = 0.f, v2 = 0.f, v3 = 0.f;

    float4 nxt[kGroup];
#pragma unroll
    for (int g = 0; g < kGroup; ++g)
        nxt[g] = *reinterpret_cast<const float4*>(pin + (long long)g * kNPB);

    constexpr int kNG = kChunk / kGroup;   // 25 super-iterations
    for (int gi = 0; gi < kNG; ++gi) {
        float4 cur[kGroup];
#pragma unroll
        for (int g = 0; g < kGroup; ++g) cur[g] = nxt[g];

        // Prefetch next group's 4 independent loads before touching smem:
        // they drain behind the two barriers + transpose/store phase.
        if (gi + 1 < kNG) {
            const float* pn = pin + (long long)(gi + 1) * kGroup * kNPB;
#pragma unroll
            for (int g = 0; g < kGroup; ++g)
                nxt[g] = *reinterpret_cast<const float4*>(pn + (long long)g * kNPB);
        }

#pragma unroll
        for (int g = 0; g < kGroup; ++g) {
            const float4 c = cur[g];
            float s0, s1, s2, s3;
            v0 += c.x; s0 = (v0 > kTh) ? 1.f : 0.f; v0 = (v0 > kTh) ? 0.f : v0;
            v1 += c.y; s1 = (v1 > kTh) ? 1.f : 0.f; v1 = (v1 > kTh) ? 0.f : v1;
            v2 += c.z; s2 = (v2 > kTh) ? 1.f : 0.f; v2 = (v2 > kTh) ? 0.f : v2;
            v3 += c.w; s3 = (v3 > kTh) ? 1.f : 0.f; v3 = (v3 > kTh) ? 0.f : v3;
            sm[g][row][q * 4 + 0] = s0;
            sm[g][row][q * 4 + 1] = s1;
            sm[g][row][q * 4 + 2] = s2;
            sm[g][row][q * 4 + 3] = s3;
        }
        __syncthreads();

#pragma unroll
        for (int g = 0; g < kGroup; ++g) {
            float4 o;
            o.x = sm[g][q * 4 + 0][row];
            o.y = sm[g][q * 4 + 1][row];
            o.z = sm[g][q * 4 + 2][row];
            o.w = sm[g][q * 4 + 3][row];
            *reinterpret_cast<float4*>(pout + (long long)(gi * kGroup + g) * kNPB) = o;
        }
        __syncthreads();
    }
}

extern "C" void kernel_launch(void* const* d_in, const int* in_sizes, int n_in,
                              void* d_out, int out_size) {
    (void)in_sizes; (void)n_in; (void)out_size;
    const float* in = (const float*)d_in[0];
    float* out = (float*)d_out;
    dim3 grid(kWC / 32, kH / 32, 4 * 2);   // 16 x 2 x 8 = 256 blocks
    integrator_kernel<<<grid, 256>>>(in, out);
}

// round 3
// speedup vs baseline: 1.0390x; 1.0390x over previous
#include <cuda_runtime.h>

// Integrate-and-fire scan fused with per-timestep 64x512 transpose.
//   v += x[t]; if (v > 2.0f) { spike[t] = 1; v = 0; }  (reset at t=100)
// R2: 1 neuron/thread, 8(h) x 32(wc) tiles -> 1024 blocks (occupancy was
// grid-limited at 256 blocks / 21% occ). Both sides remain 32B-sector
// efficient; stores are STG.128 via smem transpose.

namespace {
constexpr int kH     = 64;
constexpr int kWC    = 512;                      // W*C = 64*8
constexpr int kChunk = 100;
constexpr int kNPB   = kH * kWC;                 // 32768 neurons per batch
constexpr long long kBS = 200LL * kNPB;          // batch stride (elements)
constexpr int kGroup = 4;                        // timesteps per super-iteration
constexpr int kNG    = kChunk / kGroup;          // 25
constexpr float kTh  = 2.0f;
}

__global__ void __launch_bounds__(256)
integrator_kernel(const float* __restrict__ in, float* __restrict__ out) {
    __shared__ float sm[kGroup][32][9];   // [t-slice][wc][h], pad 9

    const int tid = threadIdx.x;
    const int wcl = tid & 31;             // 0..31  (load side: contiguous wc)
    const int hl  = tid >> 5;             // 0..7
    const int wc0 = blockIdx.x * 32;
    const int h0  = blockIdx.y * 8;
    const int b   = blockIdx.z >> 1;
    const int t0  = (blockIdx.z & 1) * kChunk;

    const float* pin = in + b * kBS + (long long)t0 * kNPB
                          + (h0 + hl) * kWC + wc0 + wcl;

    // Store side: 64 threads per t-slice, each stores one float4 of h.
    const int g2  = tid >> 6;             // 0..3   t-slice within group
    const int idx = tid & 63;
    const int wr  = idx >> 1;             // 0..31  wc row
    const int hq  = (idx & 1) * 4;        // 0 or 4 h quad
    float* pout = out + b * kBS + (long long)t0 * kNPB
                      + (wc0 + wr) * 64 + h0 + hq;

    float v = 0.f;

    float nxt[kGroup];
#pragma unroll
    for (int g = 0; g < kGroup; ++g)
        nxt[g] = pin[(long long)g * kNPB];

    for (int gi = 0; gi < kNG; ++gi) {
        float cur[kGroup];
#pragma unroll
        for (int g = 0; g < kGroup; ++g) cur[g] = nxt[g];

        // Prefetch next group's loads; they drain behind the barriers +
        // transpose/store phase.
        if (gi + 1 < kNG) {
            const float* pn = pin + (long long)(gi + 1) * kGroup * kNPB;
#pragma unroll
            for (int g = 0; g < kGroup; ++g)
                nxt[g] = pn[(long long)g * kNPB];
        }

#pragma unroll
        for (int g = 0; g < kGroup; ++g) {
            v += cur[g];
            const bool fire = v > kTh;
            sm[g][wcl][hl] = fire ? 1.f : 0.f;
            v = fire ? 0.f : v;
        }
        __syncthreads();

        float4 o;
        o.x = sm[g2][wr][hq + 0];
        o.y = sm[g2][wr][hq + 1];
        o.z = sm[g2][wr][hq + 2];
        o.w = sm[g2][wr][hq + 3];
        *reinterpret_cast<float4*>(pout + (long long)(gi * kGroup + g2) * kNPB) = o;
        __syncthreads();
    }
}

extern "C" void kernel_launch(void* const* d_in, const int* in_sizes, int n_in,
                              void* d_out, int out_size) {
    (void)in_sizes; (void)n_in; (void)out_size;
    const float* in = (const float*)d_in[0];
    float* out = (float*)d_out;
    dim3 grid(kWC / 32, kH / 8, 4 * 2);   // 16 x 8 x 8 = 1024 blocks
    integrator_kernel<<<grid, 256>>>(in, out);
}